// round 14
// baseline (speedup 1.0000x reference)
#include <cuda_runtime.h>

#define D      1024
#define BATCH  64
#define KSPLIT 16
#define KSLICE (D / KSPLIT)      // 64
#define NTILES (D / 64)          // 16
#define LOG2E  1.4426950408889634f
#define LN2    0.6931471805599453f

// ---------------- scratch (no allocations allowed) ----------------
__device__ __align__(16) float g_xl[BATCH * D];
__device__ __align__(16) float g_bl[BATCH * D];
__device__ __align__(16) float g_xs[BATCH * D];
__device__ __align__(16) float g_h1[BATCH * D];
__device__ __align__(16) float g_h2[BATCH * D];
__device__ __align__(16) float g_part[KSPLIT * BATCH * D];
__device__ unsigned g_cnt[2][NTILES];
__device__ unsigned g_done2;

__device__ __forceinline__ float ex2f(float x) {
    float r;
    asm("ex2.approx.ftz.f32 %0, %1;" : "=f"(r) : "f"(x));
    return r;
}

__device__ __forceinline__ void cexch(float& a, float& b, bool up) {
    if ((a > b) == up) { float t = a; a = b; b = t; }
}

__device__ __forceinline__ unsigned bf16pack(float x, float y) {
    unsigned r;
    asm("cvt.rn.bf16x2.f32 %0, %1, %2;" : "=r"(r) : "f"(y), "f"(x));
    return r;
}

__device__ __forceinline__ uint2 split2_bf16(float x, float y) {
    unsigned h = bf16pack(x, y);
    float hx = __uint_as_float(h << 16);
    float hy = __uint_as_float(h & 0xffff0000u);
    unsigned l = bf16pack(x - hx, y - hy);
    return make_uint2(h, l);
}

__device__ __forceinline__ void mma_bf16(float (&d)[4],
                                         unsigned a0, unsigned a1, unsigned a2, unsigned a3,
                                         unsigned b0, unsigned b1) {
    asm("mma.sync.aligned.m16n8k16.row.col.f32.bf16.bf16.f32 "
        "{%0,%1,%2,%3}, {%4,%5,%6,%7}, {%8,%9}, {%0,%1,%2,%3};"
        : "+f"(d[0]), "+f"(d[1]), "+f"(d[2]), "+f"(d[3])
        : "r"(a0), "r"(a1), "r"(a2), "r"(a3), "r"(b0), "r"(b1));
}

// ---------------- kernel 1: register-blocked bitonic sort + Bsum ----------------
__global__ void __launch_bounds__(256) sort_kernel(const float* __restrict__ x) {
    int row = blockIdx.x;
    int tid = threadIdx.x;
    __shared__ __align__(16) float sv[D];
    __shared__ float wsum[8];
    float4* sv4 = (float4*)sv;

    float4 q = ((const float4*)(x + row * D))[tid];

    cexch(q.x, q.y, true);
    cexch(q.z, q.w, false);
    {
        bool up = (tid & 1) == 0;
        cexch(q.x, q.z, up); cexch(q.y, q.w, up);
        cexch(q.x, q.y, up); cexch(q.z, q.w, up);
    }
    sv4[tid] = q;

    for (int k = 8; k <= D; k <<= 1) {
        bool upk = (tid & (k >> 2)) == 0;
        for (int j = k >> 1; j >= 4; j >>= 1) {
            __syncthreads();
            int pj = j >> 2;
            if ((tid & pj) == 0) {
                float4 a = sv4[tid];
                float4 b = sv4[tid ^ pj];
                cexch(a.x, b.x, upk); cexch(a.y, b.y, upk);
                cexch(a.z, b.z, upk); cexch(a.w, b.w, upk);
                sv4[tid] = a;
                sv4[tid ^ pj] = b;
            }
        }
        __syncthreads();
        q = sv4[tid];
        cexch(q.x, q.z, upk); cexch(q.y, q.w, upk);
        cexch(q.x, q.y, upk); cexch(q.z, q.w, upk);
        sv4[tid] = q;
    }

    float l0 = q.x;
    float l1 = l0 + q.y;
    float l2 = l1 + q.z;
    float l3 = l2 + q.w;
    int lane = tid & 31, wid = tid >> 5;
    float p = l3;
#pragma unroll
    for (int off = 1; off < 32; off <<= 1) {
        float n = __shfl_up_sync(0xffffffffu, p, off);
        if (lane >= off) p += n;
    }
    if (lane == 31) wsum[wid] = p;
    __syncthreads();
    float wbase = 0.f, S = 0.f;
#pragma unroll
    for (int w = 0; w < 8; w++) {
        float v = wsum[w];
        if (w < wid) wbase += v;
        S += v;
    }
    float base = wbase + (p - l3);

    float4 pinc = make_float4(base + l0, base + l1, base + l2, base + l3);
    int r0 = tid * 4;
    float4 bs;
    bs.x = (float)(2 * (r0 + 0) - D) * q.x + S - 2.f * (pinc.x - q.x);
    bs.y = (float)(2 * (r0 + 1) - D) * q.y + S - 2.f * (pinc.y - q.y);
    bs.z = (float)(2 * (r0 + 2) - D) * q.z + S - 2.f * (pinc.z - q.z);
    bs.w = (float)(2 * (r0 + 3) - D) * q.w + S - 2.f * (pinc.w - q.w);

    float4 xl = make_float4(q.x * LOG2E, q.y * LOG2E, q.z * LOG2E, q.w * LOG2E);
    float4 bl = make_float4(bs.x * LOG2E, bs.y * LOG2E, bs.z * LOG2E, bs.w * LOG2E);
    ((float4*)(g_xl + row * D))[tid] = xl;
    ((float4*)(g_bl + row * D))[tid] = bl;
}

// ---------------- kernel 2: windowed soft-sort, unroll-4 ----------------
__global__ void __launch_bounds__(256) softsort_kernel() {
    int row = blockIdx.y;
    int i   = blockIdx.x * blockDim.x + threadIdx.x;
    __shared__ __align__(16) float sxl[D];
    __shared__ __align__(16) float sbl[D];
    ((float4*)sxl)[threadIdx.x] = ((const float4*)(g_xl + row * D))[threadIdx.x];
    ((float4*)sbl)[threadIdx.x] = ((const float4*)(g_bl + row * D))[threadIdx.x];
    __syncthreads();

    float c  = (float)(D - 1 - 2 * i);
    int   rm = D - 1 - i;
    float mx = fmaf(c, sxl[rm], -sbl[rm]);
    float num = sxl[rm], den = 1.f;
    const float T = 22.f;

    {
        int r = rm - 1;
        for (; r >= 3; r -= 4) {
            float t0 = fmaf(c, sxl[r],     -sbl[r])     - mx;
            float t1 = fmaf(c, sxl[r - 1], -sbl[r - 1]) - mx;
            float t2 = fmaf(c, sxl[r - 2], -sbl[r - 2]) - mx;
            float t3 = fmaf(c, sxl[r - 3], -sbl[r - 3]) - mx;
            float e0 = ex2f(t0), e1 = ex2f(t1), e2 = ex2f(t2), e3 = ex2f(t3);
            den += e0; num = fmaf(e0, sxl[r],     num);
            den += e1; num = fmaf(e1, sxl[r - 1], num);
            den += e2; num = fmaf(e2, sxl[r - 2], num);
            den += e3; num = fmaf(e3, sxl[r - 3], num);
            if (t3 < -T) { r = -1; break; }
        }
        for (; r >= 0; --r) {
            float t = fmaf(c, sxl[r], -sbl[r]) - mx;
            if (t < -T) break;
            float e = ex2f(t);
            den += e; num = fmaf(e, sxl[r], num);
        }
    }
    {
        int r = rm + 1;
        for (; r < D - 3; r += 4) {
            float t0 = fmaf(c, sxl[r],     -sbl[r])     - mx;
            float t1 = fmaf(c, sxl[r + 1], -sbl[r + 1]) - mx;
            float t2 = fmaf(c, sxl[r + 2], -sbl[r + 2]) - mx;
            float t3 = fmaf(c, sxl[r + 3], -sbl[r + 3]) - mx;
            float e0 = ex2f(t0), e1 = ex2f(t1), e2 = ex2f(t2), e3 = ex2f(t3);
            den += e0; num = fmaf(e0, sxl[r],     num);
            den += e1; num = fmaf(e1, sxl[r + 1], num);
            den += e2; num = fmaf(e2, sxl[r + 2], num);
            den += e3; num = fmaf(e3, sxl[r + 3], num);
            if (t3 < -T) { r = D; break; }
        }
        for (; r < D; ++r) {
            float t = fmaf(c, sxl[r], -sbl[r]) - mx;
            if (t < -T) break;
            float e = ex2f(t);
            den += e; num = fmaf(e, sxl[r], num);
        }
    }
    g_xs[row * D + i] = num * LN2 / den;
}

// ---------------- kernel 3: split-K bf16 hi/lo GEMM + combine (+ head on layer 1) -
// Block: 64m x 64n x KSLICE(64)k, grid (16, 16) = 256 blocks = 2/SM.
__global__ void __launch_bounds__(256) gemm_fused_kernel(int layer,
                                                         const float* __restrict__ W,
                                                         const float* __restrict__ bias,
                                                         const float* __restrict__ W3,
                                                         const float* __restrict__ b3,
                                                         float* __restrict__ out) {
    const float* A = (layer == 0) ? g_xs : g_h1;
    float*       H = (layer == 0) ? g_h1 : g_h2;
    int nt   = blockIdx.x;
    int ks   = blockIdx.y;
    int tid  = threadIdx.x;
    int warp = tid >> 5;
    int lane = tid & 31;
    int mt   = warp & 3;
    int nh   = warp >> 2;
    int gid  = lane >> 2;
    int tig  = lane & 3;
    const int kbase = ks * KSLICE;

    __shared__ __align__(16) uint2 AhL[2][8][68];   // [buf][k2][m]
    __shared__ __align__(16) uint2 WhL[2][8][68];   // [buf][k2][n]
    __shared__ int s_flag;

    float acc[4][4] = {};

    int m_ld = tid >> 2;
    int k4   = (tid & 3) << 2;
    int k2   = k4 >> 1;

    float4 av = *(const float4*)&A[m_ld * D + kbase + k4];
    float4 wv = *(const float4*)&W[(nt * 64 + m_ld) * D + kbase + k4];
    AhL[0][k2 + 0][m_ld] = split2_bf16(av.x, av.y);
    AhL[0][k2 + 1][m_ld] = split2_bf16(av.z, av.w);
    WhL[0][k2 + 0][m_ld] = split2_bf16(wv.x, wv.y);
    WhL[0][k2 + 1][m_ld] = split2_bf16(wv.z, wv.w);
    __syncthreads();

#pragma unroll
    for (int c = 0; c < 4; c++) {
        int buf = c & 1;
        float4 av2, wv2;
        if (c < 3) {
            int kb = kbase + (c + 1) * 16;
            av2 = *(const float4*)&A[m_ld * D + kb + k4];
            wv2 = *(const float4*)&W[(nt * 64 + m_ld) * D + kb + k4];
        }
        {
            uint2 A0 = AhL[buf][tig][mt * 16 + gid];
            uint2 A1 = AhL[buf][tig][mt * 16 + gid + 8];
            uint2 A2 = AhL[buf][tig + 4][mt * 16 + gid];
            uint2 A3 = AhL[buf][tig + 4][mt * 16 + gid + 8];
#pragma unroll
            for (int j = 0; j < 4; j++) {
                int nc = nh * 32 + j * 8 + gid;
                uint2 B0 = WhL[buf][tig][nc];
                uint2 B1 = WhL[buf][tig + 4][nc];
                mma_bf16(acc[j], A0.x, A1.x, A2.x, A3.x, B0.x, B1.x);  // hi*hi
                mma_bf16(acc[j], A0.x, A1.x, A2.x, A3.x, B0.y, B1.y);  // hi*lo
                mma_bf16(acc[j], A0.y, A1.y, A2.y, A3.y, B0.x, B1.x);  // lo*hi
            }
        }
        if (c < 3) {
            int nb = buf ^ 1;
            AhL[nb][k2 + 0][m_ld] = split2_bf16(av2.x, av2.y);
            AhL[nb][k2 + 1][m_ld] = split2_bf16(av2.z, av2.w);
            WhL[nb][k2 + 0][m_ld] = split2_bf16(wv2.x, wv2.y);
            WhL[nb][k2 + 1][m_ld] = split2_bf16(wv2.z, wv2.w);
            __syncthreads();
        }
    }

    // write partials
#pragma unroll
    for (int j = 0; j < 4; j++) {
        int n0 = nt * 64 + nh * 32 + j * 8 + 2 * tig;
        int m0 = mt * 16 + gid;
        *(float2*)&g_part[(ks * BATCH + m0)     * D + n0] = make_float2(acc[j][0], acc[j][1]);
        *(float2*)&g_part[(ks * BATCH + m0 + 8) * D + n0] = make_float2(acc[j][2], acc[j][3]);
    }

    // ---- election: last block for this n-tile does the combine ----
    __syncthreads();
    __threadfence();
    if (tid == 0) {
        unsigned old = atomicAdd(&g_cnt[layer][nt], 1u);
        s_flag = (old == KSPLIT - 1);
        if (s_flag) g_cnt[layer][nt] = 0;
    }
    __syncthreads();
    if (!s_flag) return;
    __threadfence();

#pragma unroll
    for (int t = 0; t < 4; t++) {
        int idx = t * 256 + tid;
        int m   = idx >> 4;
        int c4  = idx & 15;
        int f4  = m * (D / 4) + nt * 16 + c4;
        float4 s = ((const float4*)g_part)[(0 * BATCH + m) * (D / 4) + nt * 16 + c4];
#pragma unroll
        for (int k = 1; k < KSPLIT; k++) {
            float4 v = ((const float4*)g_part)[(k * BATCH + m) * (D / 4) + nt * 16 + c4];
            s.x += v.x; s.y += v.y; s.z += v.z; s.w += v.w;
        }
        float4 bv = ((const float4*)bias)[nt * 16 + c4];
        s.x += bv.x; s.y += bv.y; s.z += bv.z; s.w += bv.w;
        s.x = (s.x >= 0.f) ? s.x : 0.01f * s.x;
        s.y = (s.y >= 0.f) ? s.y : 0.01f * s.y;
        s.z = (s.z >= 0.f) ? s.z : 0.01f * s.z;
        s.w = (s.w >= 0.f) ? s.w : 0.01f * s.w;
        ((float4*)H)[f4] = s;
    }

    if (layer == 0) return;

    // ---- layer 1 only: last-finishing elected block computes the 64x2 head ----
    __syncthreads();
    __threadfence();
    if (tid == 0) {
        unsigned old = atomicAdd(&g_done2, 1u);
        s_flag = (old == NTILES - 1);
        if (s_flag) g_done2 = 0u;          // reset for next graph replay
    }
    __syncthreads();
    if (!s_flag) return;
    __threadfence();

    {
        int wo = warp;                      // 8 warps -> 128 outputs
#pragma unroll
        for (int o = wo; o < 2 * BATCH; o += 8) {
            int b  = o >> 1;
            int ch = o & 1;
            const float4* h = (const float4*)&g_h2[b * D];
            const float4* w = (const float4*)&W3[ch * D];
            float s = 0.f;
#pragma unroll
            for (int j = 0; j < 8; j++) {
                float4 hv = h[lane + 32 * j];
                float4 wvv = w[lane + 32 * j];
                s = fmaf(hv.x, wvv.x, s); s = fmaf(hv.y, wvv.y, s);
                s = fmaf(hv.z, wvv.z, s); s = fmaf(hv.w, wvv.w, s);
            }
#pragma unroll
            for (int off = 16; off; off >>= 1)
                s += __shfl_down_sync(0xffffffffu, s, off);
            if (lane == 0) out[o] = s + b3[ch];
        }
    }
}

extern "C" void kernel_launch(void* const* d_in, const int* in_sizes, int n_in,
                              void* d_out, int out_size) {
    const float* x  = (const float*)d_in[0];
    const float* W1 = (const float*)d_in[1];
    const float* b1 = (const float*)d_in[2];
    const float* W2 = (const float*)d_in[3];
    const float* b2 = (const float*)d_in[4];
    const float* W3 = (const float*)d_in[5];
    const float* b3 = (const float*)d_in[6];
    float* out = (float*)d_out;
    (void)in_sizes; (void)n_in; (void)out_size;

    sort_kernel<<<BATCH, 256>>>(x);
    softsort_kernel<<<dim3(D / 256, BATCH), 256>>>();
    gemm_fused_kernel<<<dim3(NTILES, KSPLIT), 256>>>(0, W1, b1, W3, b3, out);
    gemm_fused_kernel<<<dim3(NTILES, KSPLIT), 256>>>(1, W2, b2, W3, b3, out);
}

// round 15
// speedup vs baseline: 1.1137x; 1.1137x over previous
#include <cuda_runtime.h>

#define D      1024
#define BATCH  64
#define KSPLIT 8
#define KSLICE (D / KSPLIT)      // 128
#define NTILES (D / 64)          // 16
#define LOG2E  1.4426950408889634f
#define LN2    0.6931471805599453f

// ---------------- scratch (no allocations allowed) ----------------
__device__ __align__(16) float g_xl[BATCH * D];
__device__ __align__(16) float g_bl[BATCH * D];
__device__ __align__(16) float g_xs[BATCH * D];
__device__ __align__(16) float g_h1[BATCH * D];
__device__ __align__(16) float g_h2[BATCH * D];
__device__ __align__(16) float g_part[KSPLIT * BATCH * D];
__device__ unsigned g_cnt[2][NTILES];
__device__ unsigned g_done2;

__device__ __forceinline__ float ex2f(float x) {
    float r;
    asm("ex2.approx.ftz.f32 %0, %1;" : "=f"(r) : "f"(x));
    return r;
}

__device__ __forceinline__ void cexch(float& a, float& b, bool up) {
    if ((a > b) == up) { float t = a; a = b; b = t; }
}

__device__ __forceinline__ unsigned bf16pack(float x, float y) {
    unsigned r;
    asm("cvt.rn.bf16x2.f32 %0, %1, %2;" : "=r"(r) : "f"(y), "f"(x));
    return r;
}

__device__ __forceinline__ uint2 split2_bf16(float x, float y) {
    unsigned h = bf16pack(x, y);
    float hx = __uint_as_float(h << 16);
    float hy = __uint_as_float(h & 0xffff0000u);
    unsigned l = bf16pack(x - hx, y - hy);
    return make_uint2(h, l);
}

__device__ __forceinline__ void mma_bf16(float (&d)[4],
                                         unsigned a0, unsigned a1, unsigned a2, unsigned a3,
                                         unsigned b0, unsigned b1) {
    asm("mma.sync.aligned.m16n8k16.row.col.f32.bf16.bf16.f32 "
        "{%0,%1,%2,%3}, {%4,%5,%6,%7}, {%8,%9}, {%0,%1,%2,%3};"
        : "+f"(d[0]), "+f"(d[1]), "+f"(d[2]), "+f"(d[3])
        : "r"(a0), "r"(a1), "r"(a2), "r"(a3), "r"(b0), "r"(b1));
}

// ---------------- kernel 1: register-blocked bitonic sort + Bsum ----------------
__global__ void __launch_bounds__(256) sort_kernel(const float* __restrict__ x) {
    int row = blockIdx.x;
    int tid = threadIdx.x;
    __shared__ __align__(16) float sv[D];
    __shared__ float wsum[8];
    float4* sv4 = (float4*)sv;

    float4 q = ((const float4*)(x + row * D))[tid];

    cexch(q.x, q.y, true);
    cexch(q.z, q.w, false);
    {
        bool up = (tid & 1) == 0;
        cexch(q.x, q.z, up); cexch(q.y, q.w, up);
        cexch(q.x, q.y, up); cexch(q.z, q.w, up);
    }
    sv4[tid] = q;

    for (int k = 8; k <= D; k <<= 1) {
        bool upk = (tid & (k >> 2)) == 0;
        for (int j = k >> 1; j >= 4; j >>= 1) {
            __syncthreads();
            int pj = j >> 2;
            if ((tid & pj) == 0) {
                float4 a = sv4[tid];
                float4 b = sv4[tid ^ pj];
                cexch(a.x, b.x, upk); cexch(a.y, b.y, upk);
                cexch(a.z, b.z, upk); cexch(a.w, b.w, upk);
                sv4[tid] = a;
                sv4[tid ^ pj] = b;
            }
        }
        __syncthreads();
        q = sv4[tid];
        cexch(q.x, q.z, upk); cexch(q.y, q.w, upk);
        cexch(q.x, q.y, upk); cexch(q.z, q.w, upk);
        sv4[tid] = q;
    }

    float l0 = q.x;
    float l1 = l0 + q.y;
    float l2 = l1 + q.z;
    float l3 = l2 + q.w;
    int lane = tid & 31, wid = tid >> 5;
    float p = l3;
#pragma unroll
    for (int off = 1; off < 32; off <<= 1) {
        float n = __shfl_up_sync(0xffffffffu, p, off);
        if (lane >= off) p += n;
    }
    if (lane == 31) wsum[wid] = p;
    __syncthreads();
    float wbase = 0.f, S = 0.f;
#pragma unroll
    for (int w = 0; w < 8; w++) {
        float v = wsum[w];
        if (w < wid) wbase += v;
        S += v;
    }
    float base = wbase + (p - l3);

    float4 pinc = make_float4(base + l0, base + l1, base + l2, base + l3);
    int r0 = tid * 4;
    float4 bs;
    bs.x = (float)(2 * (r0 + 0) - D) * q.x + S - 2.f * (pinc.x - q.x);
    bs.y = (float)(2 * (r0 + 1) - D) * q.y + S - 2.f * (pinc.y - q.y);
    bs.z = (float)(2 * (r0 + 2) - D) * q.z + S - 2.f * (pinc.z - q.z);
    bs.w = (float)(2 * (r0 + 3) - D) * q.w + S - 2.f * (pinc.w - q.w);

    float4 xl = make_float4(q.x * LOG2E, q.y * LOG2E, q.z * LOG2E, q.w * LOG2E);
    float4 bl = make_float4(bs.x * LOG2E, bs.y * LOG2E, bs.z * LOG2E, bs.w * LOG2E);
    ((float4*)(g_xl + row * D))[tid] = xl;
    ((float4*)(g_bl + row * D))[tid] = bl;
}

// ---------------- kernel 2: windowed soft-sort, unroll-4 ----------------
__global__ void __launch_bounds__(256) softsort_kernel() {
    int row = blockIdx.y;
    int i   = blockIdx.x * blockDim.x + threadIdx.x;
    __shared__ __align__(16) float sxl[D];
    __shared__ __align__(16) float sbl[D];
    ((float4*)sxl)[threadIdx.x] = ((const float4*)(g_xl + row * D))[threadIdx.x];
    ((float4*)sbl)[threadIdx.x] = ((const float4*)(g_bl + row * D))[threadIdx.x];
    __syncthreads();

    float c  = (float)(D - 1 - 2 * i);
    int   rm = D - 1 - i;
    float mx = fmaf(c, sxl[rm], -sbl[rm]);
    float num = sxl[rm], den = 1.f;
    const float T = 22.f;

    {
        int r = rm - 1;
        for (; r >= 3; r -= 4) {
            float t0 = fmaf(c, sxl[r],     -sbl[r])     - mx;
            float t1 = fmaf(c, sxl[r - 1], -sbl[r - 1]) - mx;
            float t2 = fmaf(c, sxl[r - 2], -sbl[r - 2]) - mx;
            float t3 = fmaf(c, sxl[r - 3], -sbl[r - 3]) - mx;
            float e0 = ex2f(t0), e1 = ex2f(t1), e2 = ex2f(t2), e3 = ex2f(t3);
            den += e0; num = fmaf(e0, sxl[r],     num);
            den += e1; num = fmaf(e1, sxl[r - 1], num);
            den += e2; num = fmaf(e2, sxl[r - 2], num);
            den += e3; num = fmaf(e3, sxl[r - 3], num);
            if (t3 < -T) { r = -1; break; }
        }
        for (; r >= 0; --r) {
            float t = fmaf(c, sxl[r], -sbl[r]) - mx;
            if (t < -T) break;
            float e = ex2f(t);
            den += e; num = fmaf(e, sxl[r], num);
        }
    }
    {
        int r = rm + 1;
        for (; r < D - 3; r += 4) {
            float t0 = fmaf(c, sxl[r],     -sbl[r])     - mx;
            float t1 = fmaf(c, sxl[r + 1], -sbl[r + 1]) - mx;
            float t2 = fmaf(c, sxl[r + 2], -sbl[r + 2]) - mx;
            float t3 = fmaf(c, sxl[r + 3], -sbl[r + 3]) - mx;
            float e0 = ex2f(t0), e1 = ex2f(t1), e2 = ex2f(t2), e3 = ex2f(t3);
            den += e0; num = fmaf(e0, sxl[r],     num);
            den += e1; num = fmaf(e1, sxl[r + 1], num);
            den += e2; num = fmaf(e2, sxl[r + 2], num);
            den += e3; num = fmaf(e3, sxl[r + 3], num);
            if (t3 < -T) { r = D; break; }
        }
        for (; r < D; ++r) {
            float t = fmaf(c, sxl[r], -sbl[r]) - mx;
            if (t < -T) break;
            float e = ex2f(t);
            den += e; num = fmaf(e, sxl[r], num);
        }
    }
    g_xs[row * D + i] = num * LN2 / den;
}

// ---------------- kernel 3: split-K bf16 hi/lo GEMM + combine (+ head, layer 1) --
// R13 config: 64m x 64n x 128k, KSPLIT=8, grid (16,8) = 128 blocks.
__global__ void __launch_bounds__(256) gemm_fused_kernel(int layer,
                                                         const float* __restrict__ W,
                                                         const float* __restrict__ bias,
                                                         const float* __restrict__ W3,
                                                         const float* __restrict__ b3,
                                                         float* __restrict__ out) {
    const float* A = (layer == 0) ? g_xs : g_h1;
    float*       H = (layer == 0) ? g_h1 : g_h2;
    int nt   = blockIdx.x;
    int ks   = blockIdx.y;
    int tid  = threadIdx.x;
    int warp = tid >> 5;
    int lane = tid & 31;
    int mt   = warp & 3;
    int nh   = warp >> 2;
    int gid  = lane >> 2;
    int tig  = lane & 3;
    const int kbase = ks * KSLICE;

    __shared__ __align__(16) uint2 AhL[2][8][68];   // [buf][k2][m]
    __shared__ __align__(16) uint2 WhL[2][8][68];   // [buf][k2][n]
    __shared__ int s_flag;

    float acc[4][4] = {};

    int m_ld = tid >> 2;
    int k4   = (tid & 3) << 2;
    int k2   = k4 >> 1;

    float4 av = *(const float4*)&A[m_ld * D + kbase + k4];
    float4 wv = *(const float4*)&W[(nt * 64 + m_ld) * D + kbase + k4];
    AhL[0][k2 + 0][m_ld] = split2_bf16(av.x, av.y);
    AhL[0][k2 + 1][m_ld] = split2_bf16(av.z, av.w);
    WhL[0][k2 + 0][m_ld] = split2_bf16(wv.x, wv.y);
    WhL[0][k2 + 1][m_ld] = split2_bf16(wv.z, wv.w);
    __syncthreads();

#pragma unroll
    for (int c = 0; c < 8; c++) {
        int buf = c & 1;
        float4 av2, wv2;
        if (c < 7) {
            int kb = kbase + (c + 1) * 16;
            av2 = *(const float4*)&A[m_ld * D + kb + k4];
            wv2 = *(const float4*)&W[(nt * 64 + m_ld) * D + kb + k4];
        }
        {
            uint2 A0 = AhL[buf][tig][mt * 16 + gid];
            uint2 A1 = AhL[buf][tig][mt * 16 + gid + 8];
            uint2 A2 = AhL[buf][tig + 4][mt * 16 + gid];
            uint2 A3 = AhL[buf][tig + 4][mt * 16 + gid + 8];
#pragma unroll
            for (int j = 0; j < 4; j++) {
                int nc = nh * 32 + j * 8 + gid;
                uint2 B0 = WhL[buf][tig][nc];
                uint2 B1 = WhL[buf][tig + 4][nc];
                mma_bf16(acc[j], A0.x, A1.x, A2.x, A3.x, B0.x, B1.x);  // hi*hi
                mma_bf16(acc[j], A0.x, A1.x, A2.x, A3.x, B0.y, B1.y);  // hi*lo
                mma_bf16(acc[j], A0.y, A1.y, A2.y, A3.y, B0.x, B1.x);  // lo*hi
            }
        }
        if (c < 7) {
            int nb = buf ^ 1;
            AhL[nb][k2 + 0][m_ld] = split2_bf16(av2.x, av2.y);
            AhL[nb][k2 + 1][m_ld] = split2_bf16(av2.z, av2.w);
            WhL[nb][k2 + 0][m_ld] = split2_bf16(wv2.x, wv2.y);
            WhL[nb][k2 + 1][m_ld] = split2_bf16(wv2.z, wv2.w);
            __syncthreads();
        }
    }

    // write partials
#pragma unroll
    for (int j = 0; j < 4; j++) {
        int n0 = nt * 64 + nh * 32 + j * 8 + 2 * tig;
        int m0 = mt * 16 + gid;
        *(float2*)&g_part[(ks * BATCH + m0)     * D + n0] = make_float2(acc[j][0], acc[j][1]);
        *(float2*)&g_part[(ks * BATCH + m0 + 8) * D + n0] = make_float2(acc[j][2], acc[j][3]);
    }

    // ---- election: last block for this n-tile does the combine ----
    __syncthreads();
    __threadfence();
    if (tid == 0) {
        unsigned old = atomicAdd(&g_cnt[layer][nt], 1u);
        s_flag = (old == KSPLIT - 1);
        if (s_flag) g_cnt[layer][nt] = 0;
    }
    __syncthreads();
    if (!s_flag) return;
    __threadfence();

#pragma unroll
    for (int t = 0; t < 4; t++) {
        int idx = t * 256 + tid;
        int m   = idx >> 4;
        int c4  = idx & 15;
        int f4  = m * (D / 4) + nt * 16 + c4;
        float4 s = ((const float4*)g_part)[(0 * BATCH + m) * (D / 4) + nt * 16 + c4];
#pragma unroll
        for (int k = 1; k < KSPLIT; k++) {
            float4 v = ((const float4*)g_part)[(k * BATCH + m) * (D / 4) + nt * 16 + c4];
            s.x += v.x; s.y += v.y; s.z += v.z; s.w += v.w;
        }
        float4 bv = ((const float4*)bias)[nt * 16 + c4];
        s.x += bv.x; s.y += bv.y; s.z += bv.z; s.w += bv.w;
        s.x = (s.x >= 0.f) ? s.x : 0.01f * s.x;
        s.y = (s.y >= 0.f) ? s.y : 0.01f * s.y;
        s.z = (s.z >= 0.f) ? s.z : 0.01f * s.z;
        s.w = (s.w >= 0.f) ? s.w : 0.01f * s.w;
        ((float4*)H)[f4] = s;
    }

    if (layer == 0) return;

    // ---- layer 1: the 16th-finishing elected block computes the 64x2 head ----
    __syncthreads();
    __threadfence();
    if (tid == 0) {
        unsigned old = atomicAdd(&g_done2, 1u);
        s_flag = (old == NTILES - 1);
        if (s_flag) g_done2 = 0u;          // reset for next graph replay
    }
    __syncthreads();
    if (!s_flag) return;
    __threadfence();

    {
#pragma unroll
        for (int o = warp; o < 2 * BATCH; o += 8) {
            int b  = o >> 1;
            int ch = o & 1;
            const float4* h = (const float4*)&g_h2[b * D];
            const float4* w = (const float4*)&W3[ch * D];
            float s = 0.f;
#pragma unroll
            for (int j = 0; j < 8; j++) {
                float4 hv = h[lane + 32 * j];
                float4 wvv = w[lane + 32 * j];
                s = fmaf(hv.x, wvv.x, s); s = fmaf(hv.y, wvv.y, s);
                s = fmaf(hv.z, wvv.z, s); s = fmaf(hv.w, wvv.w, s);
            }
#pragma unroll
            for (int off = 16; off; off >>= 1)
                s += __shfl_down_sync(0xffffffffu, s, off);
            if (lane == 0) out[o] = s + b3[ch];
        }
    }
}

extern "C" void kernel_launch(void* const* d_in, const int* in_sizes, int n_in,
                              void* d_out, int out_size) {
    const float* x  = (const float*)d_in[0];
    const float* W1 = (const float*)d_in[1];
    const float* b1 = (const float*)d_in[2];
    const float* W2 = (const float*)d_in[3];
    const float* b2 = (const float*)d_in[4];
    const float* W3 = (const float*)d_in[5];
    const float* b3 = (const float*)d_in[6];
    float* out = (float*)d_out;
    (void)in_sizes; (void)n_in; (void)out_size;

    sort_kernel<<<BATCH, 256>>>(x);
    softsort_kernel<<<dim3(D / 256, BATCH), 256>>>();
    gemm_fused_kernel<<<dim3(NTILES, KSPLIT), 256>>>(0, W1, b1, W3, b3, out);
    gemm_fused_kernel<<<dim3(NTILES, KSPLIT), 256>>>(1, W2, b2, W3, b3, out);
}

// round 16
// speedup vs baseline: 1.2418x; 1.1150x over previous
#include <cuda_runtime.h>

#define D      1024
#define BATCH  64
#define KSPLIT 8
#define KSLICE (D / KSPLIT)      // 128
#define NTILES (D / 64)          // 16
#define NBLK   16                // blocks per n-tile: 2 m-halves x 8 k-splits
#define LOG2E  1.4426950408889634f
#define LN2    0.6931471805599453f

// ---------------- scratch (no allocations allowed) ----------------
__device__ __align__(16) float g_xl[BATCH * D];
__device__ __align__(16) float g_bl[BATCH * D];
__device__ __align__(16) float g_xs[BATCH * D];
__device__ __align__(16) float g_h1[BATCH * D];
__device__ __align__(16) float g_h2[BATCH * D];
__device__ __align__(16) float g_part[KSPLIT * BATCH * D];
__device__ unsigned g_cnt[2][NTILES];

__device__ __forceinline__ float ex2f(float x) {
    float r;
    asm("ex2.approx.ftz.f32 %0, %1;" : "=f"(r) : "f"(x));
    return r;
}

__device__ __forceinline__ void cexch(float& a, float& b, bool up) {
    if ((a > b) == up) { float t = a; a = b; b = t; }
}

__device__ __forceinline__ unsigned bf16pack(float x, float y) {
    unsigned r;
    asm("cvt.rn.bf16x2.f32 %0, %1, %2;" : "=r"(r) : "f"(y), "f"(x));
    return r;
}

__device__ __forceinline__ uint2 split2_bf16(float x, float y) {
    unsigned h = bf16pack(x, y);
    float hx = __uint_as_float(h << 16);
    float hy = __uint_as_float(h & 0xffff0000u);
    unsigned l = bf16pack(x - hx, y - hy);
    return make_uint2(h, l);
}

__device__ __forceinline__ void mma_bf16(float (&d)[4],
                                         unsigned a0, unsigned a1, unsigned a2, unsigned a3,
                                         unsigned b0, unsigned b1) {
    asm("mma.sync.aligned.m16n8k16.row.col.f32.bf16.bf16.f32 "
        "{%0,%1,%2,%3}, {%4,%5,%6,%7}, {%8,%9}, {%0,%1,%2,%3};"
        : "+f"(d[0]), "+f"(d[1]), "+f"(d[2]), "+f"(d[3])
        : "r"(a0), "r"(a1), "r"(a2), "r"(a3), "r"(b0), "r"(b1));
}

// ---------------- kernel 1: register-blocked bitonic sort + Bsum ----------------
__global__ void __launch_bounds__(256) sort_kernel(const float* __restrict__ x) {
    int row = blockIdx.x;
    int tid = threadIdx.x;
    __shared__ __align__(16) float sv[D];
    __shared__ float wsum[8];
    float4* sv4 = (float4*)sv;

    float4 q = ((const float4*)(x + row * D))[tid];

    cexch(q.x, q.y, true);
    cexch(q.z, q.w, false);
    {
        bool up = (tid & 1) == 0;
        cexch(q.x, q.z, up); cexch(q.y, q.w, up);
        cexch(q.x, q.y, up); cexch(q.z, q.w, up);
    }
    sv4[tid] = q;

    for (int k = 8; k <= D; k <<= 1) {
        bool upk = (tid & (k >> 2)) == 0;
        for (int j = k >> 1; j >= 4; j >>= 1) {
            __syncthreads();
            int pj = j >> 2;
            if ((tid & pj) == 0) {
                float4 a = sv4[tid];
                float4 b = sv4[tid ^ pj];
                cexch(a.x, b.x, upk); cexch(a.y, b.y, upk);
                cexch(a.z, b.z, upk); cexch(a.w, b.w, upk);
                sv4[tid] = a;
                sv4[tid ^ pj] = b;
            }
        }
        __syncthreads();
        q = sv4[tid];
        cexch(q.x, q.z, upk); cexch(q.y, q.w, upk);
        cexch(q.x, q.y, upk); cexch(q.z, q.w, upk);
        sv4[tid] = q;
    }

    float l0 = q.x;
    float l1 = l0 + q.y;
    float l2 = l1 + q.z;
    float l3 = l2 + q.w;
    int lane = tid & 31, wid = tid >> 5;
    float p = l3;
#pragma unroll
    for (int off = 1; off < 32; off <<= 1) {
        float n = __shfl_up_sync(0xffffffffu, p, off);
        if (lane >= off) p += n;
    }
    if (lane == 31) wsum[wid] = p;
    __syncthreads();
    float wbase = 0.f, S = 0.f;
#pragma unroll
    for (int w = 0; w < 8; w++) {
        float v = wsum[w];
        if (w < wid) wbase += v;
        S += v;
    }
    float base = wbase + (p - l3);

    float4 pinc = make_float4(base + l0, base + l1, base + l2, base + l3);
    int r0 = tid * 4;
    float4 bs;
    bs.x = (float)(2 * (r0 + 0) - D) * q.x + S - 2.f * (pinc.x - q.x);
    bs.y = (float)(2 * (r0 + 1) - D) * q.y + S - 2.f * (pinc.y - q.y);
    bs.z = (float)(2 * (r0 + 2) - D) * q.z + S - 2.f * (pinc.z - q.z);
    bs.w = (float)(2 * (r0 + 3) - D) * q.w + S - 2.f * (pinc.w - q.w);

    float4 xl = make_float4(q.x * LOG2E, q.y * LOG2E, q.z * LOG2E, q.w * LOG2E);
    float4 bl = make_float4(bs.x * LOG2E, bs.y * LOG2E, bs.z * LOG2E, bs.w * LOG2E);
    ((float4*)(g_xl + row * D))[tid] = xl;
    ((float4*)(g_bl + row * D))[tid] = bl;
}

// ---------------- kernel 2: windowed soft-sort, unroll-4 ----------------
__global__ void __launch_bounds__(256) softsort_kernel() {
    int row = blockIdx.y;
    int i   = blockIdx.x * blockDim.x + threadIdx.x;
    __shared__ __align__(16) float sxl[D];
    __shared__ __align__(16) float sbl[D];
    ((float4*)sxl)[threadIdx.x] = ((const float4*)(g_xl + row * D))[threadIdx.x];
    ((float4*)sbl)[threadIdx.x] = ((const float4*)(g_bl + row * D))[threadIdx.x];
    __syncthreads();

    float c  = (float)(D - 1 - 2 * i);
    int   rm = D - 1 - i;
    float mx = fmaf(c, sxl[rm], -sbl[rm]);
    float num = sxl[rm], den = 1.f;
    const float T = 22.f;

    {
        int r = rm - 1;
        for (; r >= 3; r -= 4) {
            float t0 = fmaf(c, sxl[r],     -sbl[r])     - mx;
            float t1 = fmaf(c, sxl[r - 1], -sbl[r - 1]) - mx;
            float t2 = fmaf(c, sxl[r - 2], -sbl[r - 2]) - mx;
            float t3 = fmaf(c, sxl[r - 3], -sbl[r - 3]) - mx;
            float e0 = ex2f(t0), e1 = ex2f(t1), e2 = ex2f(t2), e3 = ex2f(t3);
            den += e0; num = fmaf(e0, sxl[r],     num);
            den += e1; num = fmaf(e1, sxl[r - 1], num);
            den += e2; num = fmaf(e2, sxl[r - 2], num);
            den += e3; num = fmaf(e3, sxl[r - 3], num);
            if (t3 < -T) { r = -1; break; }
        }
        for (; r >= 0; --r) {
            float t = fmaf(c, sxl[r], -sbl[r]) - mx;
            if (t < -T) break;
            float e = ex2f(t);
            den += e; num = fmaf(e, sxl[r], num);
        }
    }
    {
        int r = rm + 1;
        for (; r < D - 3; r += 4) {
            float t0 = fmaf(c, sxl[r],     -sbl[r])     - mx;
            float t1 = fmaf(c, sxl[r + 1], -sbl[r + 1]) - mx;
            float t2 = fmaf(c, sxl[r + 2], -sbl[r + 2]) - mx;
            float t3 = fmaf(c, sxl[r + 3], -sbl[r + 3]) - mx;
            float e0 = ex2f(t0), e1 = ex2f(t1), e2 = ex2f(t2), e3 = ex2f(t3);
            den += e0; num = fmaf(e0, sxl[r],     num);
            den += e1; num = fmaf(e1, sxl[r + 1], num);
            den += e2; num = fmaf(e2, sxl[r + 2], num);
            den += e3; num = fmaf(e3, sxl[r + 3], num);
            if (t3 < -T) { r = D; break; }
        }
        for (; r < D; ++r) {
            float t = fmaf(c, sxl[r], -sbl[r]) - mx;
            if (t < -T) break;
            float e = ex2f(t);
            den += e; num = fmaf(e, sxl[r], num);
        }
    }
    g_xs[row * D + i] = num * LN2 / den;
}

// ---------------- kernel 3: split-K+M bf16 hi/lo GEMM + fused combine ------------
// Block: 32m x 64n x 128k. grid (16 nt, 16 = ks*2+mh) = 256 blocks (~2/SM).
// 8 warps: mt = w&1 (16 m-rows), nh = w>>1 (16 n-cols via 2 j-tiles of 8).
__global__ void __launch_bounds__(256) gemm_fused_kernel(int layer,
                                                         const float* __restrict__ W,
                                                         const float* __restrict__ bias) {
    const float* A = (layer == 0) ? g_xs : g_h1;
    float*       H = (layer == 0) ? g_h1 : g_h2;
    int nt   = blockIdx.x;
    int ks   = blockIdx.y >> 1;
    int mh   = blockIdx.y & 1;
    int tid  = threadIdx.x;
    int warp = tid >> 5;
    int lane = tid & 31;
    int mt   = warp & 1;
    int nh   = warp >> 1;          // 0..3
    int gid  = lane >> 2;
    int tig  = lane & 3;
    const int kbase = ks * KSLICE;
    const int mbase = mh * 32;

    __shared__ __align__(16) uint2 AhL[2][8][36];   // [buf][k2][m 0..31]
    __shared__ __align__(16) uint2 WhL[2][8][68];   // [buf][k2][n 0..63]
    __shared__ int s_flag;

    float acc[2][4] = {};          // [j][c0..c3]

    int m_ld = tid >> 2;           // 0..63 (W rows; A rows use tid<128 -> 0..31)
    int k4   = (tid & 3) << 2;     // 0,4,8,12
    int k2   = k4 >> 1;            // 0,2,4,6
    bool aldr = (tid < 128);

    float4 av = make_float4(0.f, 0.f, 0.f, 0.f);
    if (aldr) av = *(const float4*)&A[(mbase + m_ld) * D + kbase + k4];
    float4 wv = *(const float4*)&W[(nt * 64 + m_ld) * D + kbase + k4];
    if (aldr) {
        AhL[0][k2 + 0][m_ld] = split2_bf16(av.x, av.y);
        AhL[0][k2 + 1][m_ld] = split2_bf16(av.z, av.w);
    }
    WhL[0][k2 + 0][m_ld] = split2_bf16(wv.x, wv.y);
    WhL[0][k2 + 1][m_ld] = split2_bf16(wv.z, wv.w);
    __syncthreads();

#pragma unroll
    for (int c = 0; c < 8; c++) {
        int buf = c & 1;
        float4 av2, wv2;
        if (c < 7) {
            int kb = kbase + (c + 1) * 16;
            if (aldr) av2 = *(const float4*)&A[(mbase + m_ld) * D + kb + k4];
            wv2 = *(const float4*)&W[(nt * 64 + m_ld) * D + kb + k4];
        }
        {
            uint2 A0 = AhL[buf][tig][mt * 16 + gid];
            uint2 A1 = AhL[buf][tig][mt * 16 + gid + 8];
            uint2 A2 = AhL[buf][tig + 4][mt * 16 + gid];
            uint2 A3 = AhL[buf][tig + 4][mt * 16 + gid + 8];
#pragma unroll
            for (int j = 0; j < 2; j++) {
                int nc = nh * 16 + j * 8 + gid;
                uint2 B0 = WhL[buf][tig][nc];
                uint2 B1 = WhL[buf][tig + 4][nc];
                mma_bf16(acc[j], A0.x, A1.x, A2.x, A3.x, B0.x, B1.x);  // hi*hi
                mma_bf16(acc[j], A0.x, A1.x, A2.x, A3.x, B0.y, B1.y);  // hi*lo
                mma_bf16(acc[j], A0.y, A1.y, A2.y, A3.y, B0.x, B1.x);  // lo*hi
            }
        }
        if (c < 7) {
            int nb = buf ^ 1;
            if (aldr) {
                AhL[nb][k2 + 0][m_ld] = split2_bf16(av2.x, av2.y);
                AhL[nb][k2 + 1][m_ld] = split2_bf16(av2.z, av2.w);
            }
            WhL[nb][k2 + 0][m_ld] = split2_bf16(wv2.x, wv2.y);
            WhL[nb][k2 + 1][m_ld] = split2_bf16(wv2.z, wv2.w);
            __syncthreads();
        }
    }

    // write partials: rows mbase + mt*16 + gid (+8), cols nt*64 + nh*16 + j*8 + 2tig
#pragma unroll
    for (int j = 0; j < 2; j++) {
        int n0 = nt * 64 + nh * 16 + j * 8 + 2 * tig;
        int m0 = mbase + mt * 16 + gid;
        *(float2*)&g_part[(ks * BATCH + m0)     * D + n0] = make_float2(acc[j][0], acc[j][1]);
        *(float2*)&g_part[(ks * BATCH + m0 + 8) * D + n0] = make_float2(acc[j][2], acc[j][3]);
    }

    // ---- election: last of the 16 blocks for this n-tile does the combine ----
    __syncthreads();
    __threadfence();
    if (tid == 0) {
        unsigned old = atomicAdd(&g_cnt[layer][nt], 1u);
        s_flag = (old == NBLK - 1);
        if (s_flag) g_cnt[layer][nt] = 0;
    }
    __syncthreads();
    if (!s_flag) return;
    __threadfence();

#pragma unroll
    for (int t = 0; t < 4; t++) {
        int idx = t * 256 + tid;
        int m   = idx >> 4;
        int c4  = idx & 15;
        int f4  = m * (D / 4) + nt * 16 + c4;
        float4 s = ((const float4*)g_part)[(0 * BATCH + m) * (D / 4) + nt * 16 + c4];
#pragma unroll
        for (int k = 1; k < KSPLIT; k++) {
            float4 v = ((const float4*)g_part)[(k * BATCH + m) * (D / 4) + nt * 16 + c4];
            s.x += v.x; s.y += v.y; s.z += v.z; s.w += v.w;
        }
        float4 bv = ((const float4*)bias)[nt * 16 + c4];
        s.x += bv.x; s.y += bv.y; s.z += bv.z; s.w += bv.w;
        s.x = (s.x >= 0.f) ? s.x : 0.01f * s.x;
        s.y = (s.y >= 0.f) ? s.y : 0.01f * s.y;
        s.z = (s.z >= 0.f) ? s.z : 0.01f * s.z;
        s.w = (s.w >= 0.f) ? s.w : 0.01f * s.w;
        ((float4*)H)[f4] = s;
    }
}

// ---------------- kernel 4: final 1024 -> 2 head ----------------
__global__ void __launch_bounds__(256) final_kernel(const float* __restrict__ W3,
                                                    const float* __restrict__ b3,
                                                    float* __restrict__ out) {
    int b   = blockIdx.x;
    int tid = threadIdx.x;
    int c   = tid >> 7;
    int j0  = tid & 127;
    float acc = 0.f;
#pragma unroll
    for (int t = 0; t < 8; t++) {
        int j = j0 + (t << 7);
        acc = fmaf(g_h2[b * D + j], W3[c * D + j], acc);
    }
    __shared__ float red[8];
#pragma unroll
    for (int off = 16; off; off >>= 1)
        acc += __shfl_down_sync(0xffffffffu, acc, off);
    if ((tid & 31) == 0) red[tid >> 5] = acc;
    __syncthreads();
    if (tid < 2) {
        float s = (red[tid * 4] + red[tid * 4 + 1]) +
                  (red[tid * 4 + 2] + red[tid * 4 + 3]);
        out[b * 2 + tid] = s + b3[tid];
    }
}

extern "C" void kernel_launch(void* const* d_in, const int* in_sizes, int n_in,
                              void* d_out, int out_size) {
    const float* x  = (const float*)d_in[0];
    const float* W1 = (const float*)d_in[1];
    const float* b1 = (const float*)d_in[2];
    const float* W2 = (const float*)d_in[3];
    const float* b2 = (const float*)d_in[4];
    const float* W3 = (const float*)d_in[5];
    const float* b3 = (const float*)d_in[6];
    float* out = (float*)d_out;
    (void)in_sizes; (void)n_in; (void)out_size;

    sort_kernel<<<BATCH, 256>>>(x);
    softsort_kernel<<<dim3(D / 256, BATCH), 256>>>();
    gemm_fused_kernel<<<dim3(NTILES, NBLK), 256>>>(0, W1, b1);
    gemm_fused_kernel<<<dim3(NTILES, NBLK), 256>>>(1, W2, b2);
    final_kernel<<<BATCH, 256>>>(W3, b3, out);
}

// round 17
// speedup vs baseline: 1.3195x; 1.0626x over previous
#include <cuda_runtime.h>

#define D      1024
#define BATCH  64
#define KSPLIT 8
#define KSLICE (D / KSPLIT)      // 128
#define NTILES (D / 64)          // 16
#define LOG2E  1.4426950408889634f
#define LN2    0.6931471805599453f

// ---------------- scratch (no allocations allowed) ----------------
__device__ __align__(16) float g_xl[BATCH * D];
__device__ __align__(16) float g_bl[BATCH * D];
__device__ __align__(16) float g_xs[BATCH * D];
__device__ __align__(16) float g_h1[BATCH * D];
__device__ __align__(16) float g_h2[BATCH * D];
__device__ __align__(16) float g_part[KSPLIT * BATCH * D];
__device__ unsigned g_cnt[2][NTILES];

__device__ __forceinline__ float ex2f(float x) {
    float r;
    asm("ex2.approx.ftz.f32 %0, %1;" : "=f"(r) : "f"(x));
    return r;
}

__device__ __forceinline__ void cexch(float& a, float& b, bool up) {
    if ((a > b) == up) { float t = a; a = b; b = t; }
}

__device__ __forceinline__ unsigned bf16pack(float x, float y) {
    unsigned r;
    asm("cvt.rn.bf16x2.f32 %0, %1, %2;" : "=r"(r) : "f"(y), "f"(x));
    return r;
}

__device__ __forceinline__ uint2 split2_bf16(float x, float y) {
    unsigned h = bf16pack(x, y);
    float hx = __uint_as_float(h << 16);
    float hy = __uint_as_float(h & 0xffff0000u);
    unsigned l = bf16pack(x - hx, y - hy);
    return make_uint2(h, l);
}

__device__ __forceinline__ void mma_bf16(float (&d)[4],
                                         unsigned a0, unsigned a1, unsigned a2, unsigned a3,
                                         unsigned b0, unsigned b1) {
    asm("mma.sync.aligned.m16n8k16.row.col.f32.bf16.bf16.f32 "
        "{%0,%1,%2,%3}, {%4,%5,%6,%7}, {%8,%9}, {%0,%1,%2,%3};"
        : "+f"(d[0]), "+f"(d[1]), "+f"(d[2]), "+f"(d[3])
        : "r"(a0), "r"(a1), "r"(a2), "r"(a3), "r"(b0), "r"(b1));
}

// ---------------- kernel 1: register-blocked bitonic sort + Bsum ----------------
__global__ void __launch_bounds__(256) sort_kernel(const float* __restrict__ x) {
    int row = blockIdx.x;
    int tid = threadIdx.x;
    __shared__ __align__(16) float sv[D];
    __shared__ float wsum[8];
    float4* sv4 = (float4*)sv;

    float4 q = ((const float4*)(x + row * D))[tid];

    cexch(q.x, q.y, true);
    cexch(q.z, q.w, false);
    {
        bool up = (tid & 1) == 0;
        cexch(q.x, q.z, up); cexch(q.y, q.w, up);
        cexch(q.x, q.y, up); cexch(q.z, q.w, up);
    }
    sv4[tid] = q;

    for (int k = 8; k <= D; k <<= 1) {
        bool upk = (tid & (k >> 2)) == 0;
        for (int j = k >> 1; j >= 4; j >>= 1) {
            __syncthreads();
            int pj = j >> 2;
            if ((tid & pj) == 0) {
                float4 a = sv4[tid];
                float4 b = sv4[tid ^ pj];
                cexch(a.x, b.x, upk); cexch(a.y, b.y, upk);
                cexch(a.z, b.z, upk); cexch(a.w, b.w, upk);
                sv4[tid] = a;
                sv4[tid ^ pj] = b;
            }
        }
        __syncthreads();
        q = sv4[tid];
        cexch(q.x, q.z, upk); cexch(q.y, q.w, upk);
        cexch(q.x, q.y, upk); cexch(q.z, q.w, upk);
        sv4[tid] = q;
    }

    float l0 = q.x;
    float l1 = l0 + q.y;
    float l2 = l1 + q.z;
    float l3 = l2 + q.w;
    int lane = tid & 31, wid = tid >> 5;
    float p = l3;
#pragma unroll
    for (int off = 1; off < 32; off <<= 1) {
        float n = __shfl_up_sync(0xffffffffu, p, off);
        if (lane >= off) p += n;
    }
    if (lane == 31) wsum[wid] = p;
    __syncthreads();
    float wbase = 0.f, S = 0.f;
#pragma unroll
    for (int w = 0; w < 8; w++) {
        float v = wsum[w];
        if (w < wid) wbase += v;
        S += v;
    }
    float base = wbase + (p - l3);

    float4 pinc = make_float4(base + l0, base + l1, base + l2, base + l3);
    int r0 = tid * 4;
    float4 bs;
    bs.x = (float)(2 * (r0 + 0) - D) * q.x + S - 2.f * (pinc.x - q.x);
    bs.y = (float)(2 * (r0 + 1) - D) * q.y + S - 2.f * (pinc.y - q.y);
    bs.z = (float)(2 * (r0 + 2) - D) * q.z + S - 2.f * (pinc.z - q.z);
    bs.w = (float)(2 * (r0 + 3) - D) * q.w + S - 2.f * (pinc.w - q.w);

    float4 xl = make_float4(q.x * LOG2E, q.y * LOG2E, q.z * LOG2E, q.w * LOG2E);
    float4 bl = make_float4(bs.x * LOG2E, bs.y * LOG2E, bs.z * LOG2E, bs.w * LOG2E);
    ((float4*)(g_xl + row * D))[tid] = xl;
    ((float4*)(g_bl + row * D))[tid] = bl;
}

// ---------------- kernel 2: windowed soft-sort, unroll-4 ----------------
__global__ void __launch_bounds__(256) softsort_kernel() {
    int row = blockIdx.y;
    int i   = blockIdx.x * blockDim.x + threadIdx.x;
    __shared__ __align__(16) float sxl[D];
    __shared__ __align__(16) float sbl[D];
    ((float4*)sxl)[threadIdx.x] = ((const float4*)(g_xl + row * D))[threadIdx.x];
    ((float4*)sbl)[threadIdx.x] = ((const float4*)(g_bl + row * D))[threadIdx.x];
    __syncthreads();

    float c  = (float)(D - 1 - 2 * i);
    int   rm = D - 1 - i;
    float mx = fmaf(c, sxl[rm], -sbl[rm]);
    float num = sxl[rm], den = 1.f;
    const float T = 22.f;

    {
        int r = rm - 1;
        for (; r >= 3; r -= 4) {
            float t0 = fmaf(c, sxl[r],     -sbl[r])     - mx;
            float t1 = fmaf(c, sxl[r - 1], -sbl[r - 1]) - mx;
            float t2 = fmaf(c, sxl[r - 2], -sbl[r - 2]) - mx;
            float t3 = fmaf(c, sxl[r - 3], -sbl[r - 3]) - mx;
            float e0 = ex2f(t0), e1 = ex2f(t1), e2 = ex2f(t2), e3 = ex2f(t3);
            den += e0; num = fmaf(e0, sxl[r],     num);
            den += e1; num = fmaf(e1, sxl[r - 1], num);
            den += e2; num = fmaf(e2, sxl[r - 2], num);
            den += e3; num = fmaf(e3, sxl[r - 3], num);
            if (t3 < -T) { r = -1; break; }
        }
        for (; r >= 0; --r) {
            float t = fmaf(c, sxl[r], -sbl[r]) - mx;
            if (t < -T) break;
            float e = ex2f(t);
            den += e; num = fmaf(e, sxl[r], num);
        }
    }
    {
        int r = rm + 1;
        for (; r < D - 3; r += 4) {
            float t0 = fmaf(c, sxl[r],     -sbl[r])     - mx;
            float t1 = fmaf(c, sxl[r + 1], -sbl[r + 1]) - mx;
            float t2 = fmaf(c, sxl[r + 2], -sbl[r + 2]) - mx;
            float t3 = fmaf(c, sxl[r + 3], -sbl[r + 3]) - mx;
            float e0 = ex2f(t0), e1 = ex2f(t1), e2 = ex2f(t2), e3 = ex2f(t3);
            den += e0; num = fmaf(e0, sxl[r],     num);
            den += e1; num = fmaf(e1, sxl[r + 1], num);
            den += e2; num = fmaf(e2, sxl[r + 2], num);
            den += e3; num = fmaf(e3, sxl[r + 3], num);
            if (t3 < -T) { r = D; break; }
        }
        for (; r < D; ++r) {
            float t = fmaf(c, sxl[r], -sbl[r]) - mx;
            if (t < -T) break;
            float e = ex2f(t);
            den += e; num = fmaf(e, sxl[r], num);
        }
    }
    g_xs[row * D + i] = num * LN2 / den;
}

// ---------------- kernel 3: split-K bf16 hi/lo GEMM, 32k stages + fused combine --
// R13 config (64m x 64n x 128k, KSPLIT=8, grid 128) with 4 stages of 32k
// (half the barriers, double the per-stage ILP and prefetch distance).
__global__ void __launch_bounds__(256) gemm_fused_kernel(int layer,
                                                         const float* __restrict__ W,
                                                         const float* __restrict__ bias) {
    const float* A = (layer == 0) ? g_xs : g_h1;
    float*       H = (layer == 0) ? g_h1 : g_h2;
    int nt   = blockIdx.x;
    int ks   = blockIdx.y;
    int tid  = threadIdx.x;
    int warp = tid >> 5;
    int lane = tid & 31;
    int mt   = warp & 3;
    int nh   = warp >> 2;
    int gid  = lane >> 2;
    int tig  = lane & 3;
    const int kbase = ks * KSLICE;

    __shared__ __align__(16) uint2 AhL[2][16][68];   // [buf][k2 (32k)][m]
    __shared__ __align__(16) uint2 WhL[2][16][68];   // [buf][k2][n]
    __shared__ int s_flag;

    float acc[4][4] = {};

    int m_ld = tid >> 2;
    int k4   = (tid & 3) << 2;     // 0,4,8,12 within first 16k half
    int k2   = k4 >> 1;            // 0,2,4,6

    // prologue: load stage 0 (32 k)
    {
        float4 a0 = *(const float4*)&A[m_ld * D + kbase + k4];
        float4 a1 = *(const float4*)&A[m_ld * D + kbase + k4 + 16];
        float4 w0 = *(const float4*)&W[(nt * 64 + m_ld) * D + kbase + k4];
        float4 w1 = *(const float4*)&W[(nt * 64 + m_ld) * D + kbase + k4 + 16];
        AhL[0][k2 + 0][m_ld] = split2_bf16(a0.x, a0.y);
        AhL[0][k2 + 1][m_ld] = split2_bf16(a0.z, a0.w);
        AhL[0][k2 + 8][m_ld] = split2_bf16(a1.x, a1.y);
        AhL[0][k2 + 9][m_ld] = split2_bf16(a1.z, a1.w);
        WhL[0][k2 + 0][m_ld] = split2_bf16(w0.x, w0.y);
        WhL[0][k2 + 1][m_ld] = split2_bf16(w0.z, w0.w);
        WhL[0][k2 + 8][m_ld] = split2_bf16(w1.x, w1.y);
        WhL[0][k2 + 9][m_ld] = split2_bf16(w1.z, w1.w);
    }
    __syncthreads();

#pragma unroll
    for (int c = 0; c < 4; c++) {
        int buf = c & 1;
        float4 a0n, a1n, w0n, w1n;
        if (c < 3) {
            int kb = kbase + (c + 1) * 32;
            a0n = *(const float4*)&A[m_ld * D + kb + k4];
            a1n = *(const float4*)&A[m_ld * D + kb + k4 + 16];
            w0n = *(const float4*)&W[(nt * 64 + m_ld) * D + kb + k4];
            w1n = *(const float4*)&W[(nt * 64 + m_ld) * D + kb + k4 + 16];
        }
#pragma unroll
        for (int s = 0; s < 2; s++) {
            int kr = s * 8 + tig;
            uint2 A0 = AhL[buf][kr][mt * 16 + gid];
            uint2 A1 = AhL[buf][kr][mt * 16 + gid + 8];
            uint2 A2 = AhL[buf][kr + 4][mt * 16 + gid];
            uint2 A3 = AhL[buf][kr + 4][mt * 16 + gid + 8];
#pragma unroll
            for (int j = 0; j < 4; j++) {
                int nc = nh * 32 + j * 8 + gid;
                uint2 B0 = WhL[buf][kr][nc];
                uint2 B1 = WhL[buf][kr + 4][nc];
                mma_bf16(acc[j], A0.x, A1.x, A2.x, A3.x, B0.x, B1.x);  // hi*hi
                mma_bf16(acc[j], A0.x, A1.x, A2.x, A3.x, B0.y, B1.y);  // hi*lo
                mma_bf16(acc[j], A0.y, A1.y, A2.y, A3.y, B0.x, B1.x);  // lo*hi
            }
        }
        if (c < 3) {
            int nb = buf ^ 1;
            AhL[nb][k2 + 0][m_ld] = split2_bf16(a0n.x, a0n.y);
            AhL[nb][k2 + 1][m_ld] = split2_bf16(a0n.z, a0n.w);
            AhL[nb][k2 + 8][m_ld] = split2_bf16(a1n.x, a1n.y);
            AhL[nb][k2 + 9][m_ld] = split2_bf16(a1n.z, a1n.w);
            WhL[nb][k2 + 0][m_ld] = split2_bf16(w0n.x, w0n.y);
            WhL[nb][k2 + 1][m_ld] = split2_bf16(w0n.z, w0n.w);
            WhL[nb][k2 + 8][m_ld] = split2_bf16(w1n.x, w1n.y);
            WhL[nb][k2 + 9][m_ld] = split2_bf16(w1n.z, w1n.w);
            __syncthreads();
        }
    }

    // write partials (unchanged layout)
#pragma unroll
    for (int j = 0; j < 4; j++) {
        int n0 = nt * 64 + nh * 32 + j * 8 + 2 * tig;
        int m0 = mt * 16 + gid;
        *(float2*)&g_part[(ks * BATCH + m0)     * D + n0] = make_float2(acc[j][0], acc[j][1]);
        *(float2*)&g_part[(ks * BATCH + m0 + 8) * D + n0] = make_float2(acc[j][2], acc[j][3]);
    }

    // ---- election: last block for this n-tile does the combine ----
    __syncthreads();
    __threadfence();
    if (tid == 0) {
        unsigned old = atomicAdd(&g_cnt[layer][nt], 1u);
        s_flag = (old == KSPLIT - 1);
        if (s_flag) g_cnt[layer][nt] = 0;
    }
    __syncthreads();
    if (!s_flag) return;
    __threadfence();

#pragma unroll
    for (int t = 0; t < 4; t++) {
        int idx = t * 256 + tid;
        int m   = idx >> 4;
        int c4  = idx & 15;
        int f4  = m * (D / 4) + nt * 16 + c4;
        float4 s = ((const float4*)g_part)[(0 * BATCH + m) * (D / 4) + nt * 16 + c4];
#pragma unroll
        for (int k = 1; k < KSPLIT; k++) {
            float4 v = ((const float4*)g_part)[(k * BATCH + m) * (D / 4) + nt * 16 + c4];
            s.x += v.x; s.y += v.y; s.z += v.z; s.w += v.w;
        }
        float4 bv = ((const float4*)bias)[nt * 16 + c4];
        s.x += bv.x; s.y += bv.y; s.z += bv.z; s.w += bv.w;
        s.x = (s.x >= 0.f) ? s.x : 0.01f * s.x;
        s.y = (s.y >= 0.f) ? s.y : 0.01f * s.y;
        s.z = (s.z >= 0.f) ? s.z : 0.01f * s.z;
        s.w = (s.w >= 0.f) ? s.w : 0.01f * s.w;
        ((float4*)H)[f4] = s;
    }
}

// ---------------- kernel 4: final 1024 -> 2 head ----------------
__global__ void __launch_bounds__(256) final_kernel(const float* __restrict__ W3,
                                                    const float* __restrict__ b3,
                                                    float* __restrict__ out) {
    int b   = blockIdx.x;
    int tid = threadIdx.x;
    int c   = tid >> 7;
    int j0  = tid & 127;
    float acc = 0.f;
#pragma unroll
    for (int t = 0; t < 8; t++) {
        int j = j0 + (t << 7);
        acc = fmaf(g_h2[b * D + j], W3[c * D + j], acc);
    }
    __shared__ float red[8];
#pragma unroll
    for (int off = 16; off; off >>= 1)
        acc += __shfl_down_sync(0xffffffffu, acc, off);
    if ((tid & 31) == 0) red[tid >> 5] = acc;
    __syncthreads();
    if (tid < 2) {
        float s = (red[tid * 4] + red[tid * 4 + 1]) +
                  (red[tid * 4 + 2] + red[tid * 4 + 3]);
        out[b * 2 + tid] = s + b3[tid];
    }
}

extern "C" void kernel_launch(void* const* d_in, const int* in_sizes, int n_in,
                              void* d_out, int out_size) {
    const float* x  = (const float*)d_in[0];
    const float* W1 = (const float*)d_in[1];
    const float* b1 = (const float*)d_in[2];
    const float* W2 = (const float*)d_in[3];
    const float* b2 = (const float*)d_in[4];
    const float* W3 = (const float*)d_in[5];
    const float* b3 = (const float*)d_in[6];
    float* out = (float*)d_out;
    (void)in_sizes; (void)n_in; (void)out_size;

    sort_kernel<<<BATCH, 256>>>(x);
    softsort_kernel<<<dim3(D / 256, BATCH), 256>>>();
    gemm_fused_kernel<<<dim3(NTILES, KSPLIT), 256>>>(0, W1, b1);
    gemm_fused_kernel<<<dim3(NTILES, KSPLIT), 256>>>(1, W2, b2);
    final_kernel<<<BATCH, 256>>>(W3, b3, out);
}